// round 1
// baseline (speedup 1.0000x reference)
#include <cuda_runtime.h>
#include <math.h>

// Problem constants (fixed by reference setup)
#define NN 768          // n_nuclei
#define CNT 767.0f      // edges per sender
// smem layout for edge kernel (floats)
#define PR_STRIDE 33
#define SM_PR   0
#define SM_NX   (NN*PR_STRIDE)
#define SM_NY   (SM_NX + NN)
#define SM_NZ   (SM_NY + NN)
#define SM_BASE (SM_NZ + NN)
#define SM_RED  (SM_BASE + 32)
#define SM_TOTAL (SM_RED + 256)

// ---------------- scratch (static device globals; no allocation) ----------------
__device__ float g_embed0[NN*32];
__device__ float g_base1[NN*32];   // Ps1 + mp1_b0
__device__ float g_Pr1[NN*32];
__device__ float g_acc1[NN*32];
__device__ float g_e1[NN*64];
__device__ float g_base2[NN*32];   // Ps2 + mp2_b0
__device__ float g_Pr2[NN*32];
__device__ float g_acc2[NN*32];
__device__ float g_aggsum[160];

// RBF projection weights for both layers (rows 64..95 of mp1_w0, rows 128..159 of mp2_w0)
__constant__ float cWe[2][32*32];

__device__ __forceinline__ float silu_f(float x) {
    return __fdividef(x, 1.0f + __expf(-x));
}

// ---------------- pass 0: node embeddings + layer-1 sender/receiver projections ----
__global__ void prep_kernel(const float* __restrict__ embed_table,
                            const int*   __restrict__ charges,
                            const float* __restrict__ mp1_w0,
                            const float* __restrict__ mp1_b0)
{
    int gid = blockIdx.x * blockDim.x + threadIdx.x;   // 0 .. 768*32-1
    int n = gid >> 5, j = gid & 31;
    int c = charges[n];
    const float* er = embed_table + c * 32;
    float e0 = er[j];
    g_embed0[n*32 + j] = e0;
    float a = mp1_b0[j], b = 0.0f;
    #pragma unroll
    for (int k = 0; k < 32; k++) {
        float e = er[k];
        a = fmaf(e, mp1_w0[k*32 + j],        a);
        b = fmaf(e, mp1_w0[(32 + k)*32 + j], b);
    }
    g_base1[n*32 + j] = a;
    g_Pr1  [n*32 + j] = b;
    if (gid < 160) g_aggsum[gid] = 0.0f;
}

// ---------------- edge pass (layer L): accumulate sum over receivers of silu(h) ----
template <int L>
__global__ __launch_bounds__(256) void edge_kernel(const float* __restrict__ nuclei)
{
    extern __shared__ float sm[];
    const float* base = (L == 0) ? g_base1 : g_base2;
    const float* Pr   = (L == 0) ? g_Pr1   : g_Pr2;
    float*       accO = (L == 0) ? g_acc1  : g_acc2;

    const int tid = threadIdx.x;
    const int s   = blockIdx.x;

    // stage Pr (padded stride 33), nuclei coords, sender base into smem
    for (int i = tid; i < NN*32; i += 256)
        sm[SM_PR + (i >> 5)*PR_STRIDE + (i & 31)] = Pr[i];
    for (int i = tid; i < NN; i += 256) {
        sm[SM_NX + i] = nuclei[i*3 + 0];
        sm[SM_NY + i] = nuclei[i*3 + 1];
        sm[SM_NZ + i] = nuclei[i*3 + 2];
    }
    if (tid < 32) sm[SM_BASE + tid] = base[s*32 + tid];
    __syncthreads();

    const float sx = sm[SM_NX + s], sy = sm[SM_NY + s], sz = sm[SM_NZ + s];

    float sum[32];
    #pragma unroll
    for (int j = 0; j < 32; j++) sum[j] = 0.0f;

    #pragma unroll
    for (int it = 0; it < 3; it++) {
        int r = tid + it*256;
        if (r == s) continue;
        float dx = sm[SM_NX + r] - sx;
        float dy = sm[SM_NY + r] - sy;
        float dz = sm[SM_NZ + r] - sz;
        float x = sqrtf(fmaf(dx, dx, fmaf(dy, dy, dz*dz))) + 1e-8f;
        float th = x * 0.31415926535897931f;   // pi * x / CUTOFF
        float si, co;
        sincosf(th, &si, &co);
        float twoc = co + co;

        float acc[32];
        #pragma unroll
        for (int j = 0; j < 32; j++) acc[j] = si * cWe[L][j];   // k=1 term
        float sp = si;            // sin(1*th)
        float sc = twoc * si;     // sin(2*th)
        #pragma unroll
        for (int k = 1; k < 32; k++) {
            #pragma unroll
            for (int j = 0; j < 32; j++)
                acc[j] = fmaf(sc, cWe[L][k*32 + j], acc[j]);
            float sn = fmaf(twoc, sc, -sp);
            sp = sc; sc = sn;
        }
        float pref = __fdividef(0.44721359549995794f, x);  // sqrt(2/CUTOFF)/x
        #pragma unroll
        for (int j = 0; j < 32; j++) {
            float h = fmaf(pref, acc[j], sm[SM_BASE + j] + sm[SM_PR + r*PR_STRIDE + j]);
            sum[j] += silu_f(h);
        }
    }

    // warp butterfly reduce, then cross-warp reduce in smem
    #pragma unroll
    for (int j = 0; j < 32; j++) {
        sum[j] += __shfl_xor_sync(0xffffffffu, sum[j], 16);
        sum[j] += __shfl_xor_sync(0xffffffffu, sum[j], 8);
        sum[j] += __shfl_xor_sync(0xffffffffu, sum[j], 4);
        sum[j] += __shfl_xor_sync(0xffffffffu, sum[j], 2);
        sum[j] += __shfl_xor_sync(0xffffffffu, sum[j], 1);
    }
    int warp = tid >> 5, lane = tid & 31;
    if (lane == 0) {
        #pragma unroll
        for (int j = 0; j < 32; j++) sm[SM_RED + warp*32 + j] = sum[j];
    }
    __syncthreads();
    if (tid < 32) {
        float a = 0.0f;
        #pragma unroll
        for (int w = 0; w < 8; w++) a += sm[SM_RED + w*32 + tid];
        accO[s*32 + tid] = a;
    }
}

// ---------------- pass 2: layer-1 node update + layer-2 projections ----------------
__global__ __launch_bounds__(64) void node1_kernel(
    const float* __restrict__ mp1_w1, const float* __restrict__ mp1_b1,
    const float* __restrict__ up1_w0, const float* __restrict__ up1_b0,
    const float* __restrict__ up1_w1, const float* __restrict__ up1_b1,
    const float* __restrict__ mp2_w0, const float* __restrict__ mp2_b0)
{
    int n = blockIdx.x, t = threadIdx.x;
    __shared__ float in64[64], h[64], e1[64], m[32];
    if (t < 32) {
        in64[t] = g_embed0[n*32 + t];
        m[t] = g_acc1[n*32 + t] * (1.0f / CNT);
    }
    __syncthreads();
    if (t < 32) {
        float a = mp1_b1[t];
        #pragma unroll
        for (int k = 0; k < 32; k++) a = fmaf(m[k], mp1_w1[k*32 + t], a);
        in64[32 + t] = a;
    }
    __syncthreads();
    {
        float a = up1_b0[t];
        #pragma unroll 8
        for (int k = 0; k < 64; k++) a = fmaf(in64[k], up1_w0[k*64 + t], a);
        h[t] = silu_f(a);
    }
    __syncthreads();
    {
        float a = up1_b1[t];
        #pragma unroll 8
        for (int k = 0; k < 64; k++) a = fmaf(h[k], up1_w1[k*64 + t], a);
        e1[t] = a;
        g_e1[n*64 + t] = a;
    }
    __syncthreads();
    if (t < 32) {
        float a = mp2_b0[t], b = 0.0f;
        #pragma unroll 8
        for (int k = 0; k < 64; k++) {
            float e = e1[k];
            a = fmaf(e, mp2_w0[k*32 + t],        a);
            b = fmaf(e, mp2_w0[(64 + k)*32 + t], b);
        }
        g_base2[n*32 + t] = a;
        g_Pr2  [n*32 + t] = b;
    }
}

// ---------------- pass 4: layer-2 node update + node readout + agg sum -------------
__global__ __launch_bounds__(64) void node2_kernel(
    const int*   __restrict__ charges,
    const float* __restrict__ mp2_w1, const float* __restrict__ mp2_b1,
    const float* __restrict__ up2_w0, const float* __restrict__ up2_b0,
    const float* __restrict__ up2_w1, const float* __restrict__ up2_b1,
    const float* __restrict__ no_w0,  const float* __restrict__ no_b0,
    const float* __restrict__ no_w1,  const float* __restrict__ no_embed,
    float* __restrict__ out)
{
    int n = blockIdx.x, t = threadIdx.x;
    __shared__ float agg[160], in96[96], h[64], m[32], t3[3];
    if (t < 32) {
        m[t] = g_acc2[n*32 + t] * (1.0f / CNT);
        agg[t] = g_embed0[n*32 + t];
    }
    float e1v = g_e1[n*64 + t];
    agg[32 + t] = e1v;
    in96[t] = e1v;
    __syncthreads();
    if (t < 32) {
        float a = mp2_b1[t];
        #pragma unroll
        for (int k = 0; k < 32; k++) a = fmaf(m[k], mp2_w1[k*32 + t], a);
        in96[64 + t] = a;
    }
    __syncthreads();
    {
        float a = up2_b0[t];
        #pragma unroll 8
        for (int k = 0; k < 96; k++) a = fmaf(in96[k], up2_w0[k*64 + t], a);
        h[t] = silu_f(a);
    }
    __syncthreads();
    {
        float a = up2_b1[t] + e1v;
        #pragma unroll 8
        for (int k = 0; k < 64; k++) a = fmaf(h[k], up2_w1[k*64 + t], a);
        agg[96 + t] = a;   // n_embed2 (residual)
    }
    __syncthreads();
    if (t < 3) {
        float a = no_b0[t];
        for (int k = 0; k < 160; k++) a = fmaf(agg[k], no_w0[k*3 + t], a);
        t3[t] = silu_f(a);
    }
    for (int i = t; i < 160; i += 64) atomicAdd(&g_aggsum[i], agg[i]);
    __syncthreads();
    if (t < 3) {
        int c = charges[n];
        float o = no_embed[c*3 + t];
        #pragma unroll
        for (int k = 0; k < 3; k++) o = fmaf(t3[k], no_w1[k*3 + t], o);
        out[n*3 + t] = o;
    }
}

// ---------------- pass 5: global readout ----------------
__global__ void global_kernel(const float* __restrict__ go_w0, const float* __restrict__ go_b0,
                              const float* __restrict__ go_w1, const float* __restrict__ go_b1,
                              float* __restrict__ out)
{
    __shared__ float red[256];
    int t = threadIdx.x;
    float p = 0.0f;
    if (t < 160) p = g_aggsum[t] * (1.0f / (float)NN) * go_w0[t];
    red[t] = p;
    __syncthreads();
    for (int s = 128; s > 0; s >>= 1) {
        if (t < s) red[t] += red[t + s];
        __syncthreads();
    }
    if (t == 0) {
        float hh = silu_f(red[0] + go_b0[0]);
        out[NN*3] = fmaf(hh, go_w1[0], go_b1[0]);
    }
}

// ---------------- host-side launch ----------------
extern "C" void kernel_launch(void* const* d_in, const int* in_sizes, int n_in,
                              void* d_out, int out_size)
{
    const float* nuclei      = (const float*)d_in[0];
    const int*   charges     = (const int*)  d_in[1];
    // d_in[2] = f (values known analytically: (k+1)*pi)
    const float* embed_table = (const float*)d_in[3];
    const float* mp1_w0 = (const float*)d_in[4];
    const float* mp1_b0 = (const float*)d_in[5];
    const float* mp1_w1 = (const float*)d_in[6];
    const float* mp1_b1 = (const float*)d_in[7];
    const float* up1_w0 = (const float*)d_in[8];
    const float* up1_b0 = (const float*)d_in[9];
    const float* up1_w1 = (const float*)d_in[10];
    const float* up1_b1 = (const float*)d_in[11];
    const float* mp2_w0 = (const float*)d_in[12];
    const float* mp2_b0 = (const float*)d_in[13];
    const float* mp2_w1 = (const float*)d_in[14];
    const float* mp2_b1 = (const float*)d_in[15];
    const float* up2_w0 = (const float*)d_in[16];
    const float* up2_b0 = (const float*)d_in[17];
    const float* up2_w1 = (const float*)d_in[18];
    const float* up2_b1 = (const float*)d_in[19];
    const float* no_w0  = (const float*)d_in[20];
    const float* no_b0  = (const float*)d_in[21];
    const float* no_w1  = (const float*)d_in[22];
    const float* no_emb = (const float*)d_in[23];
    const float* go_w0  = (const float*)d_in[24];
    const float* go_b0  = (const float*)d_in[25];
    const float* go_w1  = (const float*)d_in[26];
    const float* go_b1  = (const float*)d_in[27];
    float* out = (float*)d_out;

    // RBF projection weights -> constant memory (graph-capturable D2D copies)
    void* cweAddr = nullptr;
    cudaGetSymbolAddress(&cweAddr, cWe);
    cudaMemcpyAsync((char*)cweAddr,          mp1_w0 + 64*32,  32*32*sizeof(float),
                    cudaMemcpyDeviceToDevice);
    cudaMemcpyAsync((char*)cweAddr + 4096,   mp2_w0 + 128*32, 32*32*sizeof(float),
                    cudaMemcpyDeviceToDevice);

    int smemBytes = SM_TOTAL * (int)sizeof(float);
    cudaFuncSetAttribute(edge_kernel<0>, cudaFuncAttributeMaxDynamicSharedMemorySize, smemBytes);
    cudaFuncSetAttribute(edge_kernel<1>, cudaFuncAttributeMaxDynamicSharedMemorySize, smemBytes);

    prep_kernel<<<NN*32/256, 256>>>(embed_table, charges, mp1_w0, mp1_b0);
    edge_kernel<0><<<NN, 256, smemBytes>>>(nuclei);
    node1_kernel<<<NN, 64>>>(mp1_w1, mp1_b1, up1_w0, up1_b0, up1_w1, up1_b1, mp2_w0, mp2_b0);
    edge_kernel<1><<<NN, 256, smemBytes>>>(nuclei);
    node2_kernel<<<NN, 64>>>(charges, mp2_w1, mp2_b1, up2_w0, up2_b0, up2_w1, up2_b1,
                             no_w0, no_b0, no_w1, no_emb, out);
    global_kernel<<<1, 256>>>(go_w0, go_b0, go_w1, go_b1, out);
}

// round 2
// speedup vs baseline: 1.2034x; 1.2034x over previous
#include <cuda_runtime.h>
#include <math.h>

// Problem constants (fixed by reference setup)
#define NN 768          // n_nuclei
#define CNT 767.0f      // edges per sender
// smem layout for edge kernel (floats), stride 34 keeps 8B alignment for LDS.64
#define PR_STRIDE 34
#define SM_PR   0
#define SM_NX   (NN*PR_STRIDE)
#define SM_NY   (SM_NX + NN)
#define SM_NZ   (SM_NY + NN)
#define SM_BASE (SM_NZ + NN)
#define SM_RED  (SM_BASE + 32)
#define SM_TOTAL (SM_RED + 256)

typedef unsigned long long ull;

// ---------------- scratch (static device globals; no allocation) ----------------
__device__ float g_embed0[NN*32];
__device__ float g_base1[NN*32];   // Ps1 + mp1_b0
__device__ float g_Pr1[NN*32];
__device__ float g_acc1[NN*32];
__device__ float g_e1[NN*64];
__device__ float g_base2[NN*32];   // Ps2 + mp2_b0
__device__ float g_Pr2[NN*32];
__device__ float g_acc2[NN*32];
__device__ float g_aggsum[160];

// RBF projection weights (rows 64..95 of mp1_w0, rows 128..159 of mp2_w0)
__constant__ __align__(16) float cWe[2][32*32];

__device__ __forceinline__ float silu_f(float x) {
    return __fdividef(x, 1.0f + __expf(-x));
}

// ---- packed fp32x2 helpers (Blackwell) ----
__device__ __forceinline__ ull pk2(float lo, float hi) {
    ull r; asm("mov.b64 %0, {%1,%2};" : "=l"(r) : "f"(lo), "f"(hi)); return r;
}
__device__ __forceinline__ void upk2(ull v, float& lo, float& hi) {
    asm("mov.b64 {%0,%1}, %2;" : "=f"(lo), "=f"(hi) : "l"(v));
}
__device__ __forceinline__ ull fma2(ull a, ull b, ull c) {
    ull d; asm("fma.rn.f32x2 %0, %1, %2, %3;" : "=l"(d) : "l"(a), "l"(b), "l"(c)); return d;
}
__device__ __forceinline__ ull mul2(ull a, ull b) {
    ull d; asm("mul.rn.f32x2 %0, %1, %2;" : "=l"(d) : "l"(a), "l"(b)); return d;
}
__device__ __forceinline__ ull add2(ull a, ull b) {
    ull d; asm("add.rn.f32x2 %0, %1, %2;" : "=l"(d) : "l"(a), "l"(b)); return d;
}

// ---------------- pass 0: node embeddings + layer-1 sender/receiver projections ----
__global__ void prep_kernel(const float* __restrict__ embed_table,
                            const int*   __restrict__ charges,
                            const float* __restrict__ mp1_w0,
                            const float* __restrict__ mp1_b0)
{
    int gid = blockIdx.x * blockDim.x + threadIdx.x;   // 0 .. 768*32-1
    int n = gid >> 5, j = gid & 31;
    int c = charges[n];
    const float* er = embed_table + c * 32;
    float e0 = er[j];
    g_embed0[n*32 + j] = e0;
    float a = mp1_b0[j], b = 0.0f;
    #pragma unroll
    for (int k = 0; k < 32; k++) {
        float e = er[k];
        a = fmaf(e, mp1_w0[k*32 + j],        a);
        b = fmaf(e, mp1_w0[(32 + k)*32 + j], b);
    }
    g_base1[n*32 + j] = a;
    g_Pr1  [n*32 + j] = b;
    if (gid < 160) g_aggsum[gid] = 0.0f;
}

// ---------------- edge pass (layer L): sum over receivers of silu(h), packed fp32x2 ----
template <int L>
__global__ __launch_bounds__(256, 2) void edge_kernel(const float* __restrict__ nuclei)
{
    extern __shared__ float sm[];
    const float* base = (L == 0) ? g_base1 : g_base2;
    const float* Pr   = (L == 0) ? g_Pr1   : g_Pr2;
    float*       accO = (L == 0) ? g_acc1  : g_acc2;
    const ull* cw = reinterpret_cast<const ull*>(&cWe[L][0]);   // packed j-pairs

    const int tid = threadIdx.x;
    const int s   = blockIdx.x;

    // stage Pr (padded stride 34), nuclei coords, sender base into smem
    for (int i = tid; i < NN*32; i += 256)
        sm[SM_PR + (i >> 5)*PR_STRIDE + (i & 31)] = Pr[i];
    for (int i = tid; i < NN; i += 256) {
        sm[SM_NX + i] = nuclei[i*3 + 0];
        sm[SM_NY + i] = nuclei[i*3 + 1];
        sm[SM_NZ + i] = nuclei[i*3 + 2];
    }
    if (tid < 32) sm[SM_BASE + tid] = base[s*32 + tid];
    __syncthreads();

    const float sx = sm[SM_NX + s], sy = sm[SM_NY + s], sz = sm[SM_NZ + s];

    ull sum2[16];
    #pragma unroll
    for (int j = 0; j < 16; j++) sum2[j] = 0ULL;

    #pragma unroll
    for (int it = 0; it < 3; it++) {
        int r = tid + it*256;
        if (r == s) continue;
        float dx = sm[SM_NX + r] - sx;
        float dy = sm[SM_NY + r] - sy;
        float dz = sm[SM_NZ + r] - sz;
        float x = sqrtf(fmaf(dx, dx, fmaf(dy, dy, dz*dz))) + 1e-8f;
        float th = x * 0.31415926535897931f;   // pi * x / CUTOFF
        float si, co;
        sincosf(th, &si, &co);
        float twoc = co + co;

        // acc2[j2] = sum_k sin((k+1)theta) * We[k][2j2:2j2+1]   (Chebyshev recurrence)
        ull acc2[16];
        ull si2 = pk2(si, si);
        #pragma unroll
        for (int j = 0; j < 16; j++) acc2[j] = mul2(si2, cw[j]);    // k=1 term
        float sp = si;            // sin(1*th)
        float sc = twoc * si;     // sin(2*th)
        #pragma unroll
        for (int k = 1; k < 32; k++) {
            ull sc2 = pk2(sc, sc);
            #pragma unroll
            for (int j = 0; j < 16; j++)
                acc2[j] = fma2(sc2, cw[k*16 + j], acc2[j]);
            float sn = fmaf(twoc, sc, -sp);
            sp = sc; sc = sn;
        }

        float pref = __fdividef(0.44721359549995794f, x);  // sqrt(2/CUTOFF)/x
        ull pref2 = pk2(pref, pref);
        const ull* pr2p = reinterpret_cast<const ull*>(&sm[SM_PR + r*PR_STRIDE]);
        const ull* ba2p = reinterpret_cast<const ull*>(&sm[SM_BASE]);
        #pragma unroll
        for (int j = 0; j < 16; j++) {
            ull h2 = fma2(pref2, acc2[j], add2(ba2p[j], pr2p[j]));
            float hl, hh; upk2(h2, hl, hh);
            sum2[j] = add2(sum2[j], pk2(silu_f(hl), silu_f(hh)));
        }
    }

    // unpack and reduce: warp butterfly, then cross-warp in smem
    float sum[32];
    #pragma unroll
    for (int j = 0; j < 16; j++) upk2(sum2[j], sum[2*j], sum[2*j+1]);
    #pragma unroll
    for (int j = 0; j < 32; j++) {
        sum[j] += __shfl_xor_sync(0xffffffffu, sum[j], 16);
        sum[j] += __shfl_xor_sync(0xffffffffu, sum[j], 8);
        sum[j] += __shfl_xor_sync(0xffffffffu, sum[j], 4);
        sum[j] += __shfl_xor_sync(0xffffffffu, sum[j], 2);
        sum[j] += __shfl_xor_sync(0xffffffffu, sum[j], 1);
    }
    int warp = tid >> 5, lane = tid & 31;
    if (lane == 0) {
        #pragma unroll
        for (int j = 0; j < 32; j++) sm[SM_RED + warp*32 + j] = sum[j];
    }
    __syncthreads();
    if (tid < 32) {
        float a = 0.0f;
        #pragma unroll
        for (int w = 0; w < 8; w++) a += sm[SM_RED + w*32 + tid];
        accO[s*32 + tid] = a;
    }
}

// ---------------- pass 2: layer-1 node update + layer-2 projections ----------------
__global__ __launch_bounds__(64) void node1_kernel(
    const float* __restrict__ mp1_w1, const float* __restrict__ mp1_b1,
    const float* __restrict__ up1_w0, const float* __restrict__ up1_b0,
    const float* __restrict__ up1_w1, const float* __restrict__ up1_b1,
    const float* __restrict__ mp2_w0, const float* __restrict__ mp2_b0)
{
    int n = blockIdx.x, t = threadIdx.x;
    __shared__ float in64[64], h[64], e1[64], m[32];
    if (t < 32) {
        in64[t] = g_embed0[n*32 + t];
        m[t] = g_acc1[n*32 + t] * (1.0f / CNT);
    }
    __syncthreads();
    if (t < 32) {
        float a = mp1_b1[t];
        #pragma unroll
        for (int k = 0; k < 32; k++) a = fmaf(m[k], mp1_w1[k*32 + t], a);
        in64[32 + t] = a;
    }
    __syncthreads();
    {
        float a = up1_b0[t];
        #pragma unroll 8
        for (int k = 0; k < 64; k++) a = fmaf(in64[k], up1_w0[k*64 + t], a);
        h[t] = silu_f(a);
    }
    __syncthreads();
    {
        float a = up1_b1[t];
        #pragma unroll 8
        for (int k = 0; k < 64; k++) a = fmaf(h[k], up1_w1[k*64 + t], a);
        e1[t] = a;
        g_e1[n*64 + t] = a;
    }
    __syncthreads();
    if (t < 32) {
        float a = mp2_b0[t], b = 0.0f;
        #pragma unroll 8
        for (int k = 0; k < 64; k++) {
            float e = e1[k];
            a = fmaf(e, mp2_w0[k*32 + t],        a);
            b = fmaf(e, mp2_w0[(64 + k)*32 + t], b);
        }
        g_base2[n*32 + t] = a;
        g_Pr2  [n*32 + t] = b;
    }
}

// ---------------- pass 4: layer-2 node update + node readout + agg sum -------------
__global__ __launch_bounds__(64) void node2_kernel(
    const int*   __restrict__ charges,
    const float* __restrict__ mp2_w1, const float* __restrict__ mp2_b1,
    const float* __restrict__ up2_w0, const float* __restrict__ up2_b0,
    const float* __restrict__ up2_w1, const float* __restrict__ up2_b1,
    const float* __restrict__ no_w0,  const float* __restrict__ no_b0,
    const float* __restrict__ no_w1,  const float* __restrict__ no_embed,
    float* __restrict__ out)
{
    int n = blockIdx.x, t = threadIdx.x;
    __shared__ float agg[160], in96[96], h[64], m[32], t3[3];
    if (t < 32) {
        m[t] = g_acc2[n*32 + t] * (1.0f / CNT);
        agg[t] = g_embed0[n*32 + t];
    }
    float e1v = g_e1[n*64 + t];
    agg[32 + t] = e1v;
    in96[t] = e1v;
    __syncthreads();
    if (t < 32) {
        float a = mp2_b1[t];
        #pragma unroll
        for (int k = 0; k < 32; k++) a = fmaf(m[k], mp2_w1[k*32 + t], a);
        in96[64 + t] = a;
    }
    __syncthreads();
    {
        float a = up2_b0[t];
        #pragma unroll 8
        for (int k = 0; k < 96; k++) a = fmaf(in96[k], up2_w0[k*64 + t], a);
        h[t] = silu_f(a);
    }
    __syncthreads();
    {
        float a = up2_b1[t] + e1v;
        #pragma unroll 8
        for (int k = 0; k < 64; k++) a = fmaf(h[k], up2_w1[k*64 + t], a);
        agg[96 + t] = a;   // n_embed2 (residual)
    }
    __syncthreads();
    if (t < 3) {
        float a = no_b0[t];
        for (int k = 0; k < 160; k++) a = fmaf(agg[k], no_w0[k*3 + t], a);
        t3[t] = silu_f(a);
    }
    for (int i = t; i < 160; i += 64) atomicAdd(&g_aggsum[i], agg[i]);
    __syncthreads();
    if (t < 3) {
        int c = charges[n];
        float o = no_embed[c*3 + t];
        #pragma unroll
        for (int k = 0; k < 3; k++) o = fmaf(t3[k], no_w1[k*3 + t], o);
        out[n*3 + t] = o;
    }
}

// ---------------- pass 5: global readout ----------------
__global__ void global_kernel(const float* __restrict__ go_w0, const float* __restrict__ go_b0,
                              const float* __restrict__ go_w1, const float* __restrict__ go_b1,
                              float* __restrict__ out)
{
    __shared__ float red[256];
    int t = threadIdx.x;
    float p = 0.0f;
    if (t < 160) p = g_aggsum[t] * (1.0f / (float)NN) * go_w0[t];
    red[t] = p;
    __syncthreads();
    for (int s = 128; s > 0; s >>= 1) {
        if (t < s) red[t] += red[t + s];
        __syncthreads();
    }
    if (t == 0) {
        float hh = silu_f(red[0] + go_b0[0]);
        out[NN*3] = fmaf(hh, go_w1[0], go_b1[0]);
    }
}

// ---------------- host-side launch ----------------
extern "C" void kernel_launch(void* const* d_in, const int* in_sizes, int n_in,
                              void* d_out, int out_size)
{
    const float* nuclei      = (const float*)d_in[0];
    const int*   charges     = (const int*)  d_in[1];
    // d_in[2] = f (values known analytically: (k+1)*pi)
    const float* embed_table = (const float*)d_in[3];
    const float* mp1_w0 = (const float*)d_in[4];
    const float* mp1_b0 = (const float*)d_in[5];
    const float* mp1_w1 = (const float*)d_in[6];
    const float* mp1_b1 = (const float*)d_in[7];
    const float* up1_w0 = (const float*)d_in[8];
    const float* up1_b0 = (const float*)d_in[9];
    const float* up1_w1 = (const float*)d_in[10];
    const float* up1_b1 = (const float*)d_in[11];
    const float* mp2_w0 = (const float*)d_in[12];
    const float* mp2_b0 = (const float*)d_in[13];
    const float* mp2_w1 = (const float*)d_in[14];
    const float* mp2_b1 = (const float*)d_in[15];
    const float* up2_w0 = (const float*)d_in[16];
    const float* up2_b0 = (const float*)d_in[17];
    const float* up2_w1 = (const float*)d_in[18];
    const float* up2_b1 = (const float*)d_in[19];
    const float* no_w0  = (const float*)d_in[20];
    const float* no_b0  = (const float*)d_in[21];
    const float* no_w1  = (const float*)d_in[22];
    const float* no_emb = (const float*)d_in[23];
    const float* go_w0  = (const float*)d_in[24];
    const float* go_b0  = (const float*)d_in[25];
    const float* go_w1  = (const float*)d_in[26];
    const float* go_b1  = (const float*)d_in[27];
    float* out = (float*)d_out;

    // RBF projection weights -> constant memory (graph-capturable D2D copies)
    void* cweAddr = nullptr;
    cudaGetSymbolAddress(&cweAddr, cWe);
    cudaMemcpyAsync((char*)cweAddr,          mp1_w0 + 64*32,  32*32*sizeof(float),
                    cudaMemcpyDeviceToDevice);
    cudaMemcpyAsync((char*)cweAddr + 4096,   mp2_w0 + 128*32, 32*32*sizeof(float),
                    cudaMemcpyDeviceToDevice);

    int smemBytes = SM_TOTAL * (int)sizeof(float);
    cudaFuncSetAttribute(edge_kernel<0>, cudaFuncAttributeMaxDynamicSharedMemorySize, smemBytes);
    cudaFuncSetAttribute(edge_kernel<1>, cudaFuncAttributeMaxDynamicSharedMemorySize, smemBytes);

    prep_kernel<<<NN*32/256, 256>>>(embed_table, charges, mp1_w0, mp1_b0);
    edge_kernel<0><<<NN, 256, smemBytes>>>(nuclei);
    node1_kernel<<<NN, 64>>>(mp1_w1, mp1_b1, up1_w0, up1_b0, up1_w1, up1_b1, mp2_w0, mp2_b0);
    edge_kernel<1><<<NN, 256, smemBytes>>>(nuclei);
    node2_kernel<<<NN, 64>>>(charges, mp2_w1, mp2_b1, up2_w0, up2_b0, up2_w1, up2_b1,
                             no_w0, no_b0, no_w1, no_emb, out);
    global_kernel<<<1, 256>>>(go_w0, go_b0, go_w1, go_b1, out);
}

// round 3
// speedup vs baseline: 1.2925x; 1.0741x over previous
#include <cuda_runtime.h>
#include <math.h>

// Problem constants (fixed by reference setup)
#define NN 768          // n_nuclei
#define CNT 767.0f      // edges per sender
// smem layout for edge kernel (floats), stride 34 keeps 8B alignment for LDS.64
#define PR_STRIDE 34
#define SM_PR   0
#define SM_NX   (NN*PR_STRIDE)
#define SM_NY   (SM_NX + NN)
#define SM_NZ   (SM_NY + NN)
#define SM_BASE (SM_NZ + NN)
#define SM_RED  (SM_BASE + 32)
#define SM_TOTAL (SM_RED + 256)

typedef unsigned long long ull;

// ---------------- scratch (static device globals; no allocation) ----------------
__device__ float g_embed0[NN*32];
__device__ float g_base1[NN*32];   // Ps1 + mp1_b0
__device__ float g_Pr1[NN*32];
__device__ float g_acc1[NN*32];
__device__ float g_e1[NN*64];
__device__ float g_base2[NN*32];   // Ps2 + mp2_b0
__device__ float g_Pr2[NN*32];
__device__ float g_acc2[NN*32];
__device__ float g_aggsum[160];

// RBF projection weights (rows 64..95 of mp1_w0, rows 128..159 of mp2_w0)
__constant__ __align__(16) float cWe[2][32*32];

__device__ __forceinline__ float silu_f(float x) {          // exact-ish (node kernels)
    return __fdividef(x, 1.0f + __expf(-x));
}
__device__ __forceinline__ float silu_t(float x) {          // 1-MUFU (edge kernels)
    float xh = 0.5f * x, t;
    asm("tanh.approx.f32 %0, %1;" : "=f"(t) : "f"(xh));
    return fmaf(xh, t, xh);                                  // x/2*(1+tanh(x/2))
}

// ---- packed fp32x2 helpers (Blackwell) ----
__device__ __forceinline__ ull pk2(float lo, float hi) {
    ull r; asm("mov.b64 %0, {%1,%2};" : "=l"(r) : "f"(lo), "f"(hi)); return r;
}
__device__ __forceinline__ void upk2(ull v, float& lo, float& hi) {
    asm("mov.b64 {%0,%1}, %2;" : "=f"(lo), "=f"(hi) : "l"(v));
}
__device__ __forceinline__ ull fma2(ull a, ull b, ull c) {
    ull d; asm("fma.rn.f32x2 %0, %1, %2, %3;" : "=l"(d) : "l"(a), "l"(b), "l"(c)); return d;
}
__device__ __forceinline__ ull mul2(ull a, ull b) {
    ull d; asm("mul.rn.f32x2 %0, %1, %2;" : "=l"(d) : "l"(a), "l"(b)); return d;
}
__device__ __forceinline__ ull add2(ull a, ull b) {
    ull d; asm("add.rn.f32x2 %0, %1, %2;" : "=l"(d) : "l"(a), "l"(b)); return d;
}

// ---------------- pass 0: node embeddings + layer-1 sender/receiver projections ----
__global__ void prep_kernel(const float* __restrict__ embed_table,
                            const int*   __restrict__ charges,
                            const float* __restrict__ mp1_w0,
                            const float* __restrict__ mp1_b0)
{
    int gid = blockIdx.x * blockDim.x + threadIdx.x;   // 0 .. 768*32-1
    int n = gid >> 5, j = gid & 31;
    int c = charges[n];
    const float* er = embed_table + c * 32;
    float e0 = er[j];
    g_embed0[n*32 + j] = e0;
    float a = mp1_b0[j], b = 0.0f;
    #pragma unroll
    for (int k = 0; k < 32; k++) {
        float e = er[k];
        a = fmaf(e, mp1_w0[k*32 + j],        a);
        b = fmaf(e, mp1_w0[(32 + k)*32 + j], b);
    }
    g_base1[n*32 + j] = a;
    g_Pr1  [n*32 + j] = b;
    if (gid < 160) g_aggsum[gid] = 0.0f;
}

// ---------------- edge pass (layer L): sum over receivers of silu(h), packed fp32x2 ----
template <int L>
__global__ __launch_bounds__(256, 2) void edge_kernel(const float* __restrict__ nuclei)
{
    extern __shared__ float sm[];
    const float* base = (L == 0) ? g_base1 : g_base2;
    const float* Pr   = (L == 0) ? g_Pr1   : g_Pr2;
    float*       accO = (L == 0) ? g_acc1  : g_acc2;
    const ulonglong2* cw4 = reinterpret_cast<const ulonglong2*>(&cWe[L][0]); // 4 packed floats

    const int tid = threadIdx.x;
    const int s   = blockIdx.x;

    // stage Pr (padded stride 34), nuclei coords, sender base into smem
    for (int i = tid; i < NN*32; i += 256)
        sm[SM_PR + (i >> 5)*PR_STRIDE + (i & 31)] = Pr[i];
    for (int i = tid; i < NN; i += 256) {
        sm[SM_NX + i] = nuclei[i*3 + 0];
        sm[SM_NY + i] = nuclei[i*3 + 1];
        sm[SM_NZ + i] = nuclei[i*3 + 2];
    }
    if (tid < 32) sm[SM_BASE + tid] = base[s*32 + tid];
    __syncthreads();

    const float sx = sm[SM_NX + s], sy = sm[SM_NY + s], sz = sm[SM_NZ + s];

    ull sum2[16];
    #pragma unroll
    for (int j = 0; j < 16; j++) sum2[j] = 0ULL;

    #pragma unroll
    for (int it = 0; it < 3; it++) {
        int r = tid + it*256;
        if (r == s) continue;
        float dx = sm[SM_NX + r] - sx;
        float dy = sm[SM_NY + r] - sy;
        float dz = sm[SM_NZ + r] - sz;
        float d2 = fmaf(dx, dx, fmaf(dy, dy, dz*dz));
        float rsq = rsqrtf(d2);                         // 1 MUFU
        float x = d2 * rsq;                             // = sqrt(d2)
        float th = x * 0.31415926535897931f;            // pi * x / CUTOFF
        float si, co;
        __sincosf(th, &si, &co);                        // RRO + 2 MUFU
        float twoc = co + co;

        // acc2[j2] = sum_k sin((k+1)theta) * We[k][2j2:2j2+1]   (Chebyshev recurrence)
        ull acc2[16];
        ull si2 = pk2(si, si);
        #pragma unroll
        for (int j = 0; j < 8; j++) {                   // k=1 term
            ulonglong2 w = cw4[j];
            acc2[2*j]   = mul2(si2, w.x);
            acc2[2*j+1] = mul2(si2, w.y);
        }
        float sp = si;            // sin(1*th)
        float sc = twoc * si;     // sin(2*th)
        #pragma unroll
        for (int k = 1; k < 32; k++) {
            ull sc2 = pk2(sc, sc);
            #pragma unroll
            for (int j = 0; j < 8; j++) {
                ulonglong2 w = cw4[k*8 + j];
                acc2[2*j]   = fma2(sc2, w.x, acc2[2*j]);
                acc2[2*j+1] = fma2(sc2, w.y, acc2[2*j+1]);
            }
            float sn = fmaf(twoc, sc, -sp);
            sp = sc; sc = sn;
        }

        float pref = 0.44721359549995794f * rsq;        // sqrt(2/CUTOFF)/x
        ull pref2 = pk2(pref, pref);
        const ull* pr2p = reinterpret_cast<const ull*>(&sm[SM_PR + r*PR_STRIDE]);
        const ull* ba2p = reinterpret_cast<const ull*>(&sm[SM_BASE]);
        #pragma unroll
        for (int j = 0; j < 16; j++) {
            ull h2 = fma2(pref2, acc2[j], add2(ba2p[j], pr2p[j]));
            float hl, hh; upk2(h2, hl, hh);
            sum2[j] = add2(sum2[j], pk2(silu_t(hl), silu_t(hh)));
        }
    }

    // unpack and reduce: warp butterfly, then cross-warp in smem
    float sum[32];
    #pragma unroll
    for (int j = 0; j < 16; j++) upk2(sum2[j], sum[2*j], sum[2*j+1]);
    #pragma unroll
    for (int j = 0; j < 32; j++) {
        sum[j] += __shfl_xor_sync(0xffffffffu, sum[j], 16);
        sum[j] += __shfl_xor_sync(0xffffffffu, sum[j], 8);
        sum[j] += __shfl_xor_sync(0xffffffffu, sum[j], 4);
        sum[j] += __shfl_xor_sync(0xffffffffu, sum[j], 2);
        sum[j] += __shfl_xor_sync(0xffffffffu, sum[j], 1);
    }
    int warp = tid >> 5, lane = tid & 31;
    if (lane == 0) {
        #pragma unroll
        for (int j = 0; j < 32; j++) sm[SM_RED + warp*32 + j] = sum[j];
    }
    __syncthreads();
    if (tid < 32) {
        float a = 0.0f;
        #pragma unroll
        for (int w = 0; w < 8; w++) a += sm[SM_RED + w*32 + tid];
        accO[s*32 + tid] = a;
    }
}

// ---------------- pass 2: layer-1 node update + layer-2 projections ----------------
__global__ __launch_bounds__(64) void node1_kernel(
    const float* __restrict__ mp1_w1, const float* __restrict__ mp1_b1,
    const float* __restrict__ up1_w0, const float* __restrict__ up1_b0,
    const float* __restrict__ up1_w1, const float* __restrict__ up1_b1,
    const float* __restrict__ mp2_w0, const float* __restrict__ mp2_b0)
{
    int n = blockIdx.x, t = threadIdx.x;
    __shared__ float in64[64], h[64], e1[64], m[32];
    if (t < 32) {
        in64[t] = g_embed0[n*32 + t];
        m[t] = g_acc1[n*32 + t] * (1.0f / CNT);
    }
    __syncthreads();
    if (t < 32) {
        float a = mp1_b1[t];
        #pragma unroll
        for (int k = 0; k < 32; k++) a = fmaf(m[k], mp1_w1[k*32 + t], a);
        in64[32 + t] = a;
    }
    __syncthreads();
    {
        float a = up1_b0[t];
        #pragma unroll 8
        for (int k = 0; k < 64; k++) a = fmaf(in64[k], up1_w0[k*64 + t], a);
        h[t] = silu_f(a);
    }
    __syncthreads();
    {
        float a = up1_b1[t];
        #pragma unroll 8
        for (int k = 0; k < 64; k++) a = fmaf(h[k], up1_w1[k*64 + t], a);
        e1[t] = a;
        g_e1[n*64 + t] = a;
    }
    __syncthreads();
    if (t < 32) {
        float a = mp2_b0[t], b = 0.0f;
        #pragma unroll 8
        for (int k = 0; k < 64; k++) {
            float e = e1[k];
            a = fmaf(e, mp2_w0[k*32 + t],        a);
            b = fmaf(e, mp2_w0[(64 + k)*32 + t], b);
        }
        g_base2[n*32 + t] = a;
        g_Pr2  [n*32 + t] = b;
    }
}

// ---------------- pass 4: layer-2 node update + node readout + agg sum -------------
__global__ __launch_bounds__(64) void node2_kernel(
    const int*   __restrict__ charges,
    const float* __restrict__ mp2_w1, const float* __restrict__ mp2_b1,
    const float* __restrict__ up2_w0, const float* __restrict__ up2_b0,
    const float* __restrict__ up2_w1, const float* __restrict__ up2_b1,
    const float* __restrict__ no_w0,  const float* __restrict__ no_b0,
    const float* __restrict__ no_w1,  const float* __restrict__ no_embed,
    float* __restrict__ out)
{
    int n = blockIdx.x, t = threadIdx.x;
    __shared__ float agg[160], in96[96], h[64], m[32], t3[3];
    if (t < 32) {
        m[t] = g_acc2[n*32 + t] * (1.0f / CNT);
        agg[t] = g_embed0[n*32 + t];
    }
    float e1v = g_e1[n*64 + t];
    agg[32 + t] = e1v;
    in96[t] = e1v;
    __syncthreads();
    if (t < 32) {
        float a = mp2_b1[t];
        #pragma unroll
        for (int k = 0; k < 32; k++) a = fmaf(m[k], mp2_w1[k*32 + t], a);
        in96[64 + t] = a;
    }
    __syncthreads();
    {
        float a = up2_b0[t];
        #pragma unroll 8
        for (int k = 0; k < 96; k++) a = fmaf(in96[k], up2_w0[k*64 + t], a);
        h[t] = silu_f(a);
    }
    __syncthreads();
    {
        float a = up2_b1[t] + e1v;
        #pragma unroll 8
        for (int k = 0; k < 64; k++) a = fmaf(h[k], up2_w1[k*64 + t], a);
        agg[96 + t] = a;   // n_embed2 (residual)
    }
    __syncthreads();
    if (t < 3) {
        float a = no_b0[t];
        for (int k = 0; k < 160; k++) a = fmaf(agg[k], no_w0[k*3 + t], a);
        t3[t] = silu_f(a);
    }
    for (int i = t; i < 160; i += 64) atomicAdd(&g_aggsum[i], agg[i]);
    __syncthreads();
    if (t < 3) {
        int c = charges[n];
        float o = no_embed[c*3 + t];
        #pragma unroll
        for (int k = 0; k < 3; k++) o = fmaf(t3[k], no_w1[k*3 + t], o);
        out[n*3 + t] = o;
    }
}

// ---------------- pass 5: global readout ----------------
__global__ void global_kernel(const float* __restrict__ go_w0, const float* __restrict__ go_b0,
                              const float* __restrict__ go_w1, const float* __restrict__ go_b1,
                              float* __restrict__ out)
{
    __shared__ float red[256];
    int t = threadIdx.x;
    float p = 0.0f;
    if (t < 160) p = g_aggsum[t] * (1.0f / (float)NN) * go_w0[t];
    red[t] = p;
    __syncthreads();
    for (int s = 128; s > 0; s >>= 1) {
        if (t < s) red[t] += red[t + s];
        __syncthreads();
    }
    if (t == 0) {
        float hh = silu_f(red[0] + go_b0[0]);
        out[NN*3] = fmaf(hh, go_w1[0], go_b1[0]);
    }
}

// ---------------- host-side launch ----------------
extern "C" void kernel_launch(void* const* d_in, const int* in_sizes, int n_in,
                              void* d_out, int out_size)
{
    const float* nuclei      = (const float*)d_in[0];
    const int*   charges     = (const int*)  d_in[1];
    // d_in[2] = f (values known analytically: (k+1)*pi)
    const float* embed_table = (const float*)d_in[3];
    const float* mp1_w0 = (const float*)d_in[4];
    const float* mp1_b0 = (const float*)d_in[5];
    const float* mp1_w1 = (const float*)d_in[6];
    const float* mp1_b1 = (const float*)d_in[7];
    const float* up1_w0 = (const float*)d_in[8];
    const float* up1_b0 = (const float*)d_in[9];
    const float* up1_w1 = (const float*)d_in[10];
    const float* up1_b1 = (const float*)d_in[11];
    const float* mp2_w0 = (const float*)d_in[12];
    const float* mp2_b0 = (const float*)d_in[13];
    const float* mp2_w1 = (const float*)d_in[14];
    const float* mp2_b1 = (const float*)d_in[15];
    const float* up2_w0 = (const float*)d_in[16];
    const float* up2_b0 = (const float*)d_in[17];
    const float* up2_w1 = (const float*)d_in[18];
    const float* up2_b1 = (const float*)d_in[19];
    const float* no_w0  = (const float*)d_in[20];
    const float* no_b0  = (const float*)d_in[21];
    const float* no_w1  = (const float*)d_in[22];
    const float* no_emb = (const float*)d_in[23];
    const float* go_w0  = (const float*)d_in[24];
    const float* go_b0  = (const float*)d_in[25];
    const float* go_w1  = (const float*)d_in[26];
    const float* go_b1  = (const float*)d_in[27];
    float* out = (float*)d_out;

    // RBF projection weights -> constant memory (graph-capturable D2D copies)
    void* cweAddr = nullptr;
    cudaGetSymbolAddress(&cweAddr, cWe);
    cudaMemcpyAsync((char*)cweAddr,          mp1_w0 + 64*32,  32*32*sizeof(float),
                    cudaMemcpyDeviceToDevice);
    cudaMemcpyAsync((char*)cweAddr + 4096,   mp2_w0 + 128*32, 32*32*sizeof(float),
                    cudaMemcpyDeviceToDevice);

    int smemBytes = SM_TOTAL * (int)sizeof(float);
    cudaFuncSetAttribute(edge_kernel<0>, cudaFuncAttributeMaxDynamicSharedMemorySize, smemBytes);
    cudaFuncSetAttribute(edge_kernel<1>, cudaFuncAttributeMaxDynamicSharedMemorySize, smemBytes);

    prep_kernel<<<NN*32/256, 256>>>(embed_table, charges, mp1_w0, mp1_b0);
    edge_kernel<0><<<NN, 256, smemBytes>>>(nuclei);
    node1_kernel<<<NN, 64>>>(mp1_w1, mp1_b1, up1_w0, up1_b0, up1_w1, up1_b1, mp2_w0, mp2_b0);
    edge_kernel<1><<<NN, 256, smemBytes>>>(nuclei);
    node2_kernel<<<NN, 64>>>(charges, mp2_w1, mp2_b1, up2_w0, up2_b0, up2_w1, up2_b1,
                             no_w0, no_b0, no_w1, no_emb, out);
    global_kernel<<<1, 256>>>(go_w0, go_b0, go_w1, go_b1, out);
}